// round 5
// baseline (speedup 1.0000x reference)
#include <cuda_runtime.h>
#include <math.h>

// PatternBranch fused kernel for GB300 (sm_103a)
// One block per sample (256 blocks x 256 threads).
// Thread t owns channels c0 = t&63 and c1 = c0+64 (conv weights in registers),
// position group g = t>>6 covers positions [g*256, g*256+256).
// Within a warp all lanes share the position -> smem patch reads are broadcasts.

#define NTHREADS 256
#define SMEM_ROW_F 196                 // 65 cols * 3 ch = 195, padded to 196 (16B-aligned rows)
#define SMEM_FLOATS (65 * SMEM_ROW_F)  // 12740 floats = 50960 bytes
#define SMEM_BYTES (SMEM_FLOATS * 4)

__global__ __launch_bounds__(NTHREADS) void pattern_branch_kernel(
    const float* __restrict__ g_in,     // [256,64,64,3]
    const float* __restrict__ conv_w,   // [3,3,3,128]
    const float* __restrict__ conv_b,   // [128]
    const float* __restrict__ match_w,  // [128]
    const float* __restrict__ match_b,  // [1]
    const float* __restrict__ pat_w,    // [32*32*32]
    const float* __restrict__ pat_b,    // [1]
    const float* __restrict__ base_w,   // [32*32*128, 3]
    const float* __restrict__ base_b,   // [3]
    const int*   __restrict__ psi,      // [32]
    float* __restrict__ out)            // [256,3]
{
    extern __shared__ float in_s[];
    __shared__ float red[8][5];

    const int tid = threadIdx.x;
    const int b   = blockIdx.x;

    // ---- Stage input sample into smem, zero-padding row 64 and col 64 ----
    // float4 view: row stride = 49 float4 (196 floats). Data rows: 48 float4 (192 floats).
    float4* s4 = reinterpret_cast<float4*>(in_s);
    // Zero padding locations (disjoint from data fill, so no sync needed between):
    //  - float4 index r*49+48 for r in 0..64  (covers cols 192..195 = col-64 pad + slack)
    //  - row 64 data region: 64*49 + q, q in 0..47
    for (int i = tid; i < 65 + 48; i += NTHREADS) {
        if (i < 65) s4[i * 49 + 48] = make_float4(0.f, 0.f, 0.f, 0.f);
        else        s4[64 * 49 + (i - 65)] = make_float4(0.f, 0.f, 0.f, 0.f);
    }
    // Fill data rows 0..63 (global rows are 192 floats = 48 float4, 16B aligned)
    const float4* g4 = reinterpret_cast<const float4*>(g_in + (size_t)b * 12288);
    for (int i = tid; i < 64 * 48; i += NTHREADS) {
        int r = i / 48;
        int q = i - r * 48;
        s4[r * 49 + q] = g4[r * 48 + q];
    }

    // ---- Per-thread setup (overlaps with other warps' fill) ----
    const int c0  = tid & 63;
    const int c1  = c0 + 64;
    const int grp = tid >> 6;

    float w0[27], w1[27];
#pragma unroll
    for (int j = 0; j < 27; ++j) {
        w0[j] = conv_w[j * 128 + c0];
        w1[j] = conv_w[j * 128 + c1];
    }
    const float cb0 = conv_b[c0];
    const float cb1 = conv_b[c1];

    // pattern gather bitmasks: bit k set if psi[k] == my channel
    unsigned m0 = 0, m1 = 0;
#pragma unroll
    for (int k = 0; k < 32; ++k) {
        int ic = psi[k];
        if (ic == c0) m0 |= 1u << k;
        if (ic == c1) m1 |= 1u << k;
    }

    __syncthreads();

    // ---- Main fused loop: 256 positions, 2 channels each ----
    float fsum0 = 0.f, fsum1 = 0.f;       // GAP partials
    float pacc  = 0.f;                    // pattern-dot partial
    float ba0 = 0.f, ba1 = 0.f, ba2 = 0.f; // base-logit partials

    const int posBase = grp * 256;
    for (int i = 0; i < 256; ++i) {
        const int pos = posBase + i;
        const int oh = pos >> 5;
        const int ow = pos & 31;
        const float* p = in_s + (oh * 2) * SMEM_ROW_F + (ow * 2) * 3;

        float a0 = cb0, a1 = cb1;
#pragma unroll
        for (int kh = 0; kh < 3; ++kh)
#pragma unroll
            for (int kw = 0; kw < 3; ++kw)
#pragma unroll
                for (int ci = 0; ci < 3; ++ci) {
                    const int j = kh * 9 + kw * 3 + ci;
                    const float v = p[kh * SMEM_ROW_F + kw * 3 + ci];  // warp-broadcast LDS
                    a0 = fmaf(v, w0[j], a0);
                    a1 = fmaf(v, w1[j], a1);
                }
        const float f0 = fmaxf(a0, 0.f);
        const float f1 = fmaxf(a1, 0.f);
        fsum0 += f0;
        fsum1 += f1;

        // base: base_w[(pos*128 + c)*3 + j]; c1 offset = +64*3 = +192 floats
        const float* bw = base_w + ((pos * 128 + c0) * 3);
        ba0 = fmaf(f0, bw[0],   ba0);
        ba1 = fmaf(f0, bw[1],   ba1);
        ba2 = fmaf(f0, bw[2],   ba2);
        ba0 = fmaf(f1, bw[192], ba0);
        ba1 = fmaf(f1, bw[193], ba1);
        ba2 = fmaf(f1, bw[194], ba2);

        // pattern dot: only threads whose channel appears in psi
        if (m0) {
            unsigned mm = m0;
            do {
                int k = __ffs(mm) - 1;
                pacc = fmaf(f0, pat_w[pos * 32 + k], pacc);
                mm &= mm - 1;
            } while (mm);
        }
        if (m1) {
            unsigned mm = m1;
            do {
                int k = __ffs(mm) - 1;
                pacc = fmaf(f1, pat_w[pos * 32 + k], pacc);
                mm &= mm - 1;
            } while (mm);
        }
    }

    // ---- Block reduction of 5 scalars (deterministic tree) ----
    float v0 = fsum0 * match_w[c0] + fsum1 * match_w[c1];
    float v1 = pacc, v2 = ba0, v3 = ba1, v4 = ba2;
#pragma unroll
    for (int off = 16; off > 0; off >>= 1) {
        v0 += __shfl_down_sync(0xffffffffu, v0, off);
        v1 += __shfl_down_sync(0xffffffffu, v1, off);
        v2 += __shfl_down_sync(0xffffffffu, v2, off);
        v3 += __shfl_down_sync(0xffffffffu, v3, off);
        v4 += __shfl_down_sync(0xffffffffu, v4, off);
    }
    const int warp = tid >> 5;
    const int lane = tid & 31;
    if (lane == 0) {
        red[warp][0] = v0; red[warp][1] = v1; red[warp][2] = v2;
        red[warp][3] = v3; red[warp][4] = v4;
    }
    __syncthreads();

    if (tid == 0) {
        float s0 = 0.f, s1 = 0.f, s2 = 0.f, s3 = 0.f, s4v = 0.f;
#pragma unroll
        for (int w = 0; w < 8; ++w) {
            s0 += red[w][0]; s1 += red[w][1]; s2 += red[w][2];
            s3 += red[w][3]; s4v += red[w][4];
        }
        // matcher: mean over 1024 positions, then dot (reassociated)
        const float matchv = s0 * (1.0f / 1024.0f) + match_b[0];
        // pattern head
        const float plog = s1 + pat_b[0];
        const float pp = 1.0f / (1.0f + expf(-plog));
        // base head: softmax over 3 logits
        const float l0 = s2 + base_b[0];
        const float l1 = s3 + base_b[1];
        const float l2 = s4v + base_b[2];
        const float mx = fmaxf(l0, fmaxf(l1, l2));
        const float e0 = expf(l0 - mx);
        const float e1 = expf(l1 - mx);
        const float e2 = expf(l2 - mx);
        const float inv = 1.0f / (e0 + e1 + e2);

        float o0, o1, o2;
        // route: matched AND p >= 0.5  (p>=0.5 <=> plog>=0)
        if (matchv > 0.0f && plog >= 0.0f) {
            o0 = pp;
            o1 = 0.5f * (1.0f - pp);
            o2 = o1;
        } else {
            o0 = e0 * inv;
            o1 = e1 * inv;
            o2 = e2 * inv;
        }
        out[b * 3 + 0] = o0;
        out[b * 3 + 1] = o1;
        out[b * 3 + 2] = o2;
    }
}

extern "C" void kernel_launch(void* const* d_in, const int* in_sizes, int n_in,
                              void* d_out, int out_size)
{
    (void)in_sizes; (void)n_in; (void)out_size;
    const float* g_in    = (const float*)d_in[0];
    const float* conv_w  = (const float*)d_in[1];
    const float* conv_b  = (const float*)d_in[2];
    const float* match_w = (const float*)d_in[3];
    const float* match_b = (const float*)d_in[4];
    const float* pat_w   = (const float*)d_in[5];
    const float* pat_b   = (const float*)d_in[6];
    const float* base_w  = (const float*)d_in[7];
    const float* base_b  = (const float*)d_in[8];
    const int*   psi     = (const int*)d_in[9];
    float* out = (float*)d_out;

    // 50960 B dynamic smem > 48 KB default -> opt in every call (idempotent, capture-safe)
    cudaFuncSetAttribute(pattern_branch_kernel,
                         cudaFuncAttributeMaxDynamicSharedMemorySize, SMEM_BYTES);

    pattern_branch_kernel<<<256, NTHREADS, SMEM_BYTES>>>(
        g_in, conv_w, conv_b, match_w, match_b,
        pat_w, pat_b, base_w, base_b, psi, out);
}